// round 2
// baseline (speedup 1.0000x reference)
#include <cuda_runtime.h>
#include <math.h>
#include <stdint.h>

#define SEQ 2048
#define DM  1024
#define NH  16
#define DK  64
#define DFF 4096
#define NL  4

// ---------------- device scratch (no cudaMalloc allowed) ----------------
__device__ float g_q[SEQ * DM];
__device__ float g_k[SEQ * DM];
__device__ float g_v[SEQ * DM];
__device__ float g_ctx[SEQ * DM];
__device__ float g_tmp[SEQ * DM];
__device__ float g_h[SEQ * DFF];
__device__ float g_scores[(size_t)NH * SEQ * SEQ];   // 256 MB

// ---------------- tiled SGEMM ----------------
// C[M,N] = scale * (A @ B or A @ B^T) [+ bias] [gelu]
// A: [M,K] row-major, lda
// B: NN -> [K,N] row-major, ldb ;  NT -> [N,K] row-major, ldb
// batched via blockIdx.z with element strides sA/sB/sC.
// Tiles: BM=BN=64, BK=16, 256 threads, 4x4 per thread.
// Requires: M % 64 == 0, N % 64 == 0, K % 16 == 0 (true for all calls here).
template <bool TB, int EPI>
__global__ __launch_bounds__(256) void sgemm(
    const float* __restrict__ A, const float* __restrict__ B,
    const float* __restrict__ bias, float* __restrict__ C,
    int K, int lda, int ldb, int ldc,
    long long sA, long long sB, long long sC, float scale)
{
    A += sA * (long long)blockIdx.z;
    B += sB * (long long)blockIdx.z;
    C += sC * (long long)blockIdx.z;

    const int tid = threadIdx.x;
    const int tx = tid & 15;        // 0..15 -> N
    const int ty = tid >> 4;        // 0..15 -> M
    const int bm = blockIdx.y * 64;
    const int bn = blockIdx.x * 64;

    __shared__ float As[16][68];
    __shared__ float Bs[16][68];

    float acc[4][4] = {};

    const int rowL = tid >> 2;          // 0..63
    const int kL   = (tid & 3) * 4;     // 0,4,8,12
    const int kB   = tid >> 4;          // 0..15 (NN B load)
    const int nB   = (tid & 15) * 4;

    for (int k0 = 0; k0 < K; k0 += 16) {
        float4 a4 = *(const float4*)(A + (size_t)(bm + rowL) * lda + k0 + kL);
        As[kL + 0][rowL] = a4.x; As[kL + 1][rowL] = a4.y;
        As[kL + 2][rowL] = a4.z; As[kL + 3][rowL] = a4.w;

        if (TB) {
            float4 b4 = *(const float4*)(B + (size_t)(bn + rowL) * ldb + k0 + kL);
            Bs[kL + 0][rowL] = b4.x; Bs[kL + 1][rowL] = b4.y;
            Bs[kL + 2][rowL] = b4.z; Bs[kL + 3][rowL] = b4.w;
        } else {
            float4 b4 = *(const float4*)(B + (size_t)(k0 + kB) * ldb + bn + nB);
            Bs[kB][nB + 0] = b4.x; Bs[kB][nB + 1] = b4.y;
            Bs[kB][nB + 2] = b4.z; Bs[kB][nB + 3] = b4.w;
        }
        __syncthreads();

#pragma unroll
        for (int kk = 0; kk < 16; kk++) {
            float a[4], b[4];
#pragma unroll
            for (int i = 0; i < 4; i++) a[i] = As[kk][ty * 4 + i];
#pragma unroll
            for (int j = 0; j < 4; j++) b[j] = Bs[kk][tx * 4 + j];
#pragma unroll
            for (int i = 0; i < 4; i++)
#pragma unroll
                for (int j = 0; j < 4; j++)
                    acc[i][j] = fmaf(a[i], b[j], acc[i][j]);
        }
        __syncthreads();
    }

#pragma unroll
    for (int i = 0; i < 4; i++) {
        const int r = bm + ty * 4 + i;
#pragma unroll
        for (int j = 0; j < 4; j++) {
            const int c = bn + tx * 4 + j;
            float v = acc[i][j] * scale;
            if (EPI >= 1) v += bias[c];
            if (EPI == 2) {
                // tanh-approx GELU (JAX default)
                float t = v;
                v = 0.5f * t * (1.0f + tanhf(0.7978845608028654f *
                                             (t + 0.044715f * t * t * t)));
            }
            C[(size_t)r * ldc + c] = v;
        }
    }
}

// ---------------- row softmax over SEQ ----------------
__global__ __launch_bounds__(256) void softmax_k(float* __restrict__ s)
{
    float* row = s + (size_t)blockIdx.x * SEQ;
    __shared__ float red[256];
    const int tid = threadIdx.x;

    float m = -1e30f;
    for (int j = tid; j < SEQ; j += 256) m = fmaxf(m, row[j]);
    red[tid] = m; __syncthreads();
    for (int st = 128; st > 0; st >>= 1) {
        if (tid < st) red[tid] = fmaxf(red[tid], red[tid + st]);
        __syncthreads();
    }
    m = red[0]; __syncthreads();

    float sum = 0.f;
    for (int j = tid; j < SEQ; j += 256) {
        float e = __expf(row[j] - m);
        row[j] = e;
        sum += e;
    }
    red[tid] = sum; __syncthreads();
    for (int st = 128; st > 0; st >>= 1) {
        if (tid < st) red[tid] += red[tid + st];
        __syncthreads();
    }
    const float inv = 1.0f / red[0];
    for (int j = tid; j < SEQ; j += 256) row[j] *= inv;
}

// ---------------- fused residual add + LayerNorm (in-place on x) ----------------
__global__ __launch_bounds__(256) void add_ln_k(
    float* __restrict__ x, const float* __restrict__ y,
    const float* __restrict__ g, const float* __restrict__ b)
{
    __shared__ float r[DM];
    __shared__ float red[256];
    const int tid = threadIdx.x;
    const size_t off = (size_t)blockIdx.x * DM;

    float lsum = 0.f;
    for (int j = tid; j < DM; j += 256) {
        float v = x[off + j] + y[off + j];
        r[j] = v;
        lsum += v;
    }
    red[tid] = lsum; __syncthreads();
    for (int st = 128; st > 0; st >>= 1) {
        if (tid < st) red[tid] += red[tid + st];
        __syncthreads();
    }
    const float mu = red[0] * (1.0f / DM);
    __syncthreads();

    float lv = 0.f;
    for (int j = tid; j < DM; j += 256) {
        float d = r[j] - mu;
        lv += d * d;
    }
    red[tid] = lv; __syncthreads();
    for (int st = 128; st > 0; st >>= 1) {
        if (tid < st) red[tid] += red[tid + st];
        __syncthreads();
    }
    const float rstd = rsqrtf(red[0] * (1.0f / DM) + 1e-5f);

    for (int j = tid; j < DM; j += 256)
        x[off + j] = (r[j] - mu) * rstd * g[j] + b[j];
}

// ---------------- launch ----------------
extern "C" void kernel_launch(void* const* d_in, const int* in_sizes, int n_in,
                              void* d_out, int out_size)
{
    const float* x_in  = (const float*)d_in[0];
    const float* wq    = (const float*)d_in[1];
    const float* bq    = (const float*)d_in[2];
    const float* wk    = (const float*)d_in[3];
    const float* bk    = (const float*)d_in[4];
    const float* wv    = (const float*)d_in[5];
    const float* bv    = (const float*)d_in[6];
    const float* wo    = (const float*)d_in[7];
    const float* bo    = (const float*)d_in[8];
    const float* w1    = (const float*)d_in[9];
    const float* b1    = (const float*)d_in[10];
    const float* w2    = (const float*)d_in[11];
    const float* b2    = (const float*)d_in[12];
    const float* ln1g  = (const float*)d_in[13];
    const float* ln1b  = (const float*)d_in[14];
    const float* ln2g  = (const float*)d_in[15];
    const float* ln2b  = (const float*)d_in[16];

    float* x = (float*)d_out;

    float *q, *k, *v, *ctx, *tmp, *h, *sc;
    cudaGetSymbolAddress((void**)&q,   g_q);
    cudaGetSymbolAddress((void**)&k,   g_k);
    cudaGetSymbolAddress((void**)&v,   g_v);
    cudaGetSymbolAddress((void**)&ctx, g_ctx);
    cudaGetSymbolAddress((void**)&tmp, g_tmp);
    cudaGetSymbolAddress((void**)&h,   g_h);
    cudaGetSymbolAddress((void**)&sc,  g_scores);

    cudaMemcpyAsync(x, x_in, (size_t)SEQ * DM * sizeof(float),
                    cudaMemcpyDeviceToDevice);

    const dim3 gD(DM / 64, SEQ / 64);        // N=1024 projections
    const dim3 gF(DFF / 64, SEQ / 64);       // N=4096 FFN up
    const dim3 gS(SEQ / 64, SEQ / 64, NH);   // scores, batched over heads
    const dim3 gAV(1, SEQ / 64, NH);         // AV, N=64 per head

    for (int l = 0; l < NL; l++) {
        const float* Wq = wq + (size_t)l * DM * DM;
        const float* Wk = wk + (size_t)l * DM * DM;
        const float* Wv = wv + (size_t)l * DM * DM;
        const float* Wo = wo + (size_t)l * DM * DM;
        const float* W1 = w1 + (size_t)l * DM * DFF;
        const float* W2 = w2 + (size_t)l * DFF * DM;

        // Q, K, V projections: x @ W + b
        sgemm<false, 1><<<gD, 256>>>(x, Wq, bq + l * DM, q, DM, DM, DM, DM, 0, 0, 0, 1.f);
        sgemm<false, 1><<<gD, 256>>>(x, Wk, bk + l * DM, k, DM, DM, DM, DM, 0, 0, 0, 1.f);
        sgemm<false, 1><<<gD, 256>>>(x, Wv, bv + l * DM, v, DM, DM, DM, DM, 0, 0, 0, 1.f);

        // scores[h] = (Q_h @ K_h^T) / 8   (NT, batched by head via col offset 64)
        sgemm<true, 0><<<gS, 256>>>(q, k, nullptr, sc, DK, DM, DM, SEQ,
                                    64, 64, (long long)SEQ * SEQ, 0.125f);

        softmax_k<<<NH * SEQ, 256>>>(sc);

        // ctx[h] = attn[h] @ V_h   (NN, batched)
        sgemm<false, 0><<<gAV, 256>>>(sc, v, nullptr, ctx, SEQ, SEQ, DM, DM,
                                      (long long)SEQ * SEQ, 64, 64, 1.f);

        // attn_out = ctx @ Wo + bo
        sgemm<false, 1><<<gD, 256>>>(ctx, Wo, bo + l * DM, tmp, DM, DM, DM, DM, 0, 0, 0, 1.f);

        // x = LN(x + attn_out)
        add_ln_k<<<SEQ, 256>>>(x, tmp, ln1g + l * DM, ln1b + l * DM);

        // h = gelu(x @ W1 + b1)
        sgemm<false, 2><<<gF, 256>>>(x, W1, b1 + l * DFF, h, DM, DM, DFF, DFF, 0, 0, 0, 1.f);

        // ffn_out = h @ W2 + b2
        sgemm<false, 1><<<gD, 256>>>(h, W2, b2 + l * DM, tmp, DFF, DFF, DM, DM, 0, 0, 0, 1.f);

        // x = LN(x + ffn_out)
        add_ln_k<<<SEQ, 256>>>(x, tmp, ln2g + l * DM, ln2b + l * DM);
    }
}

// round 6
// speedup vs baseline: 2.2592x; 2.2592x over previous
#include <cuda_runtime.h>
#include <cuda_bf16.h>
#include <math.h>
#include <stdint.h>

#define SEQ 2048
#define DM  1024
#define NH  16
#define DK  64
#define DFF 4096
#define NL  4

typedef __nv_bfloat16 bf16;

// ---------------- device scratch (no cudaMalloc allowed) ----------------
__device__ bf16 g_wqT_h[NL * DM * DM], g_wqT_l[NL * DM * DM];
__device__ bf16 g_wkT_h[NL * DM * DM], g_wkT_l[NL * DM * DM];
__device__ bf16 g_wvT_h[NL * DM * DM], g_wvT_l[NL * DM * DM];
__device__ bf16 g_woT_h[NL * DM * DM], g_woT_l[NL * DM * DM];
__device__ bf16 g_w1T_h[NL * DM * DFF], g_w1T_l[NL * DM * DFF];
__device__ bf16 g_w2T_h[NL * DM * DFF], g_w2T_l[NL * DM * DFF];
__device__ bf16 g_xh[SEQ * DM], g_xl[SEQ * DM];
__device__ bf16 g_qh[SEQ * DM], g_ql[SEQ * DM];
__device__ bf16 g_kh[SEQ * DM], g_kl[SEQ * DM];
__device__ bf16 g_vh[SEQ * DM], g_vl[SEQ * DM];
__device__ bf16 g_vth[DM * SEQ], g_vtl[DM * SEQ];   // V^T
__device__ bf16 g_ch[SEQ * DM], g_cl[SEQ * DM];
__device__ bf16 g_hh[SEQ * DFF], g_hl[SEQ * DFF];
__device__ bf16 g_ah[(size_t)NH * SEQ * SEQ], g_al[(size_t)NH * SEQ * SEQ];
__device__ float g_sc[(size_t)NH * SEQ * SEQ];
__device__ float g_tmp[SEQ * DM];

// ---------------- small helpers ----------------
__device__ __forceinline__ float gelu_f(float v) {
    return 0.5f * v * (1.0f + tanhf(0.7978845608028654f * (v + 0.044715f * v * v * v)));
}
__device__ __forceinline__ void split_bf(float v, bf16& h, bf16& l) {
    h = __float2bfloat16(v);
    l = __float2bfloat16(v - __bfloat162float(h));
}
__device__ __forceinline__ void cpa16(uint32_t dst, const void* src) {
    asm volatile("cp.async.cg.shared.global [%0], [%1], 16;" :: "r"(dst), "l"(src));
}
#define CP_COMMIT() asm volatile("cp.async.commit_group;" ::: "memory")
#define CP_WAIT0()  asm volatile("cp.async.wait_group 0;" ::: "memory")
#define CP_WAIT1()  asm volatile("cp.async.wait_group 1;" ::: "memory")
#define LDSM4(r, a) asm volatile( \
    "ldmatrix.sync.aligned.m8n8.x4.shared.b16 {%0,%1,%2,%3}, [%4];" \
    : "=r"((r)[0]), "=r"((r)[1]), "=r"((r)[2]), "=r"((r)[3]) : "r"(a))

__device__ __forceinline__ void mma16816(float* c, const uint32_t* a, const uint32_t* b) {
    asm volatile(
        "mma.sync.aligned.m16n8k16.row.col.f32.bf16.bf16.f32 "
        "{%0,%1,%2,%3}, {%4,%5,%6,%7}, {%8,%9}, {%0,%1,%2,%3};"
        : "+f"(c[0]), "+f"(c[1]), "+f"(c[2]), "+f"(c[3])
        : "r"(a[0]), "r"(a[1]), "r"(a[2]), "r"(a[3]), "r"(b[0]), "r"(b[1]));
}
__device__ __forceinline__ uint32_t sm_addr(const void* p) {
    return (uint32_t)__cvta_generic_to_shared(p);
}

// ---------------- mma.sync GEMM, bf16x3 split, fp32 accum ----------------
// D[128, BN] tile of scale*(A @ B^T) [+bias][gelu]; A,B split hi/lo, K-contiguous.
// EPI: 0 f32*scale, 1 f32+bias, 2 split+bias, 3 split, 4 gelu(v+bias) split
template <int BN, int EPI>
__global__ __launch_bounds__(256) void mmsync(
    const bf16* __restrict__ Ah, const bf16* __restrict__ Al,
    const bf16* __restrict__ Bh, const bf16* __restrict__ Bl,
    const float* __restrict__ bias,
    float* __restrict__ Cf, bf16* __restrict__ Ch, bf16* __restrict__ Cl,
    int K, int lda, int ldb, int ldc,
    long long zA, long long zB, long long zC, float scale)
{
    constexpr int WGN = (BN == 128) ? 4 : 2;   // warps along N
    constexpr int WM  = (BN == 128) ? 64 : 32; // warp tile M
    constexpr int MF  = WM / 16;
    constexpr int NF  = 4;                     // warp tile N = 32
    constexpr int SP  = 40;                    // padded row stride (halfs), 80B

    extern __shared__ bf16 sm[];
    bf16* sAH = sm;
    bf16* sAL = sAH + 2 * 128 * SP;
    bf16* sBH = sAL + 2 * 128 * SP;
    bf16* sBL = sBH + 2 * BN * SP;

    const int tid = threadIdx.x;
    const int wid = tid >> 5;
    const int lane = tid & 31;
    const int gid = lane >> 2, tig = lane & 3;
    const int bm = blockIdx.y * 128;
    const int bn = blockIdx.x * BN;
    const int z = blockIdx.z;
    Ah += zA * z; Al += zA * z; Bh += zB * z; Bl += zB * z;

    const int wm0 = (wid / WGN) * WM;
    const int wn0 = (wid % WGN) * 32;

    float acc[MF][NF][4];
#pragma unroll
    for (int i = 0; i < MF; i++)
#pragma unroll
        for (int j = 0; j < NF; j++)
#pragma unroll
            for (int q = 0; q < 4; q++) acc[i][j][q] = 0.f;

    const int nk = K >> 5;

    auto loadStage = [&](int st, int k0) {
#pragma unroll
        for (int i = 0; i < 2; i++) {
            int ch = tid + i * 256;          // 512 chunks: row=ch/4, c=ch%4
            int row = ch >> 2, c = ch & 3;
            size_t g = (size_t)(bm + row) * lda + k0 + c * 8;
            int so = st * 128 * SP + row * SP + c * 8;
            cpa16(sm_addr(&sAH[so]), Ah + g);
            cpa16(sm_addr(&sAL[so]), Al + g);
        }
#pragma unroll
        for (int i = 0; i < BN / 64; i++) {
            int ch = tid + i * 256;
            int row = ch >> 2, c = ch & 3;
            size_t g = (size_t)(bn + row) * ldb + k0 + c * 8;
            int so = st * BN * SP + row * SP + c * 8;
            cpa16(sm_addr(&sBH[so]), Bh + g);
            cpa16(sm_addr(&sBL[so]), Bl + g);
        }
    };

    loadStage(0, 0);
    CP_COMMIT();

    for (int kt = 0; kt < nk; kt++) {
        if (kt + 1 < nk) {
            loadStage((kt + 1) & 1, (kt + 1) << 5);
            CP_COMMIT();
            CP_WAIT1();
        } else {
            CP_WAIT0();
        }
        __syncthreads();

        const int st = kt & 1;
        const bf16* aH = sAH + st * 128 * SP;
        const bf16* aL = sAL + st * 128 * SP;
        const bf16* bH = sBH + st * BN * SP;
        const bf16* bL = sBL + st * BN * SP;

#pragma unroll
        for (int kk = 0; kk < 2; kk++) {
            const int koff = kk * 16;
            uint32_t ah[MF][4], al[MF][4];
            const int ar = (lane & 15);
            const int ac = koff + ((lane >> 4) << 3);
#pragma unroll
            for (int mf = 0; mf < MF; mf++) {
                int r = wm0 + mf * 16 + ar;
                LDSM4(ah[mf], sm_addr(&aH[r * SP + ac]));
                LDSM4(al[mf], sm_addr(&aL[r * SP + ac]));
            }
            uint32_t bh[NF][2], bl[NF][2];
            const int br = (lane < 16) ? (lane & 7) : 8 + (lane & 7);
            const int bc = koff + (((lane >> 3) & 1) << 3);
#pragma unroll
            for (int nn = 0; nn < NF; nn += 2) {
                int r = wn0 + nn * 8 + br;
                uint32_t t[4];
                LDSM4(t, sm_addr(&bH[r * SP + bc]));
                bh[nn][0] = t[0]; bh[nn][1] = t[1];
                bh[nn + 1][0] = t[2]; bh[nn + 1][1] = t[3];
                LDSM4(t, sm_addr(&bL[r * SP + bc]));
                bl[nn][0] = t[0]; bl[nn][1] = t[1];
                bl[nn + 1][0] = t[2]; bl[nn + 1][1] = t[3];
            }
#pragma unroll
            for (int mf = 0; mf < MF; mf++)
#pragma unroll
                for (int nf = 0; nf < NF; nf++) {
                    mma16816(acc[mf][nf], ah[mf], bh[nf]);
                    mma16816(acc[mf][nf], ah[mf], bl[nf]);
                    mma16816(acc[mf][nf], al[mf], bh[nf]);
                }
        }
        __syncthreads();
    }

    // ---------------- epilogue ----------------
#pragma unroll
    for (int mf = 0; mf < MF; mf++) {
        const int mA = bm + wm0 + mf * 16 + gid;
        const int mB = mA + 8;
#pragma unroll
        for (int nf = 0; nf < NF; nf++) {
            const int n = bn + wn0 + nf * 8 + 2 * tig;
            float c0 = acc[mf][nf][0], c1 = acc[mf][nf][1];
            float c2 = acc[mf][nf][2], c3 = acc[mf][nf][3];
            if (EPI == 0) {
                float* C = Cf + zC * z;
                float2 u = make_float2(c0 * scale, c1 * scale);
                float2 w = make_float2(c2 * scale, c3 * scale);
                *(float2*)(C + (size_t)mA * ldc + n) = u;
                *(float2*)(C + (size_t)mB * ldc + n) = w;
            } else if (EPI == 1) {
                float b0 = bias[n], b1 = bias[n + 1];
                float* C = Cf + zC * z;
                float2 u = make_float2(c0 + b0, c1 + b1);
                float2 w = make_float2(c2 + b0, c3 + b1);
                *(float2*)(C + (size_t)mA * ldc + n) = u;
                *(float2*)(C + (size_t)mB * ldc + n) = w;
            } else {
                float b0 = 0.f, b1 = 0.f;
                if (EPI != 3) { b0 = bias[n]; b1 = bias[n + 1]; }
                float v0 = c0 + b0, v1 = c1 + b1, v2 = c2 + b0, v3 = c3 + b1;
                if (EPI == 4) {
                    v0 = gelu_f(v0); v1 = gelu_f(v1);
                    v2 = gelu_f(v2); v3 = gelu_f(v3);
                }
                bf16 h0, l0, h1, l1, h2, l2, h3, l3;
                split_bf(v0, h0, l0); split_bf(v1, h1, l1);
                split_bf(v2, h2, l2); split_bf(v3, h3, l3);
                bf16* CH = Ch + zC * z;
                bf16* CL = Cl + zC * z;
                __nv_bfloat162 p;
                p.x = h0; p.y = h1; *(__nv_bfloat162*)(CH + (size_t)mA * ldc + n) = p;
                p.x = l0; p.y = l1; *(__nv_bfloat162*)(CL + (size_t)mA * ldc + n) = p;
                p.x = h2; p.y = h3; *(__nv_bfloat162*)(CH + (size_t)mB * ldc + n) = p;
                p.x = l2; p.y = l3; *(__nv_bfloat162*)(CL + (size_t)mB * ldc + n) = p;
            }
        }
    }
}

// ---------------- transpose + split weights: W[R,C] fp32 -> WT[C,R] bf16 hi/lo ----------------
__global__ void trans_split_k(const float* __restrict__ in, bf16* __restrict__ oh,
                              bf16* __restrict__ ol, int R, int C)
{
    __shared__ float t[32][33];
    const size_t zo = (size_t)blockIdx.z * R * C;
    in += zo; oh += zo; ol += zo;
    const int r0 = blockIdx.y * 32, c0 = blockIdx.x * 32;
    const int tx = threadIdx.x, ty = threadIdx.y;
#pragma unroll
    for (int i = 0; i < 32; i += 8)
        t[ty + i][tx] = in[(size_t)(r0 + ty + i) * C + c0 + tx];
    __syncthreads();
#pragma unroll
    for (int i = 0; i < 32; i += 8) {
        float v = t[tx][ty + i];
        bf16 h, l; split_bf(v, h, l);
        size_t o = (size_t)(c0 + ty + i) * R + r0 + tx;
        oh[o] = h; ol[o] = l;
    }
}

// ---------------- transpose two bf16 matrices [R,C] -> [C,R] ----------------
__global__ void trans2_bf16_k(const bf16* __restrict__ a, bf16* __restrict__ at,
                              const bf16* __restrict__ b, bf16* __restrict__ bt,
                              int R, int C)
{
    __shared__ bf16 ta[32][33], tb[32][33];
    const int r0 = blockIdx.y * 32, c0 = blockIdx.x * 32;
    const int tx = threadIdx.x, ty = threadIdx.y;
#pragma unroll
    for (int i = 0; i < 32; i += 8) {
        size_t g = (size_t)(r0 + ty + i) * C + c0 + tx;
        ta[ty + i][tx] = a[g];
        tb[ty + i][tx] = b[g];
    }
    __syncthreads();
#pragma unroll
    for (int i = 0; i < 32; i += 8) {
        size_t o = (size_t)(c0 + ty + i) * R + r0 + tx;
        at[o] = ta[tx][ty + i];
        bt[o] = tb[tx][ty + i];
    }
}

// ---------------- elementwise split ----------------
__global__ void split_k(const float* __restrict__ x, bf16* __restrict__ h,
                        bf16* __restrict__ l, int n)
{
    int i = blockIdx.x * 256 + threadIdx.x;
    if (i < n) {
        bf16 hh, ll; split_bf(x[i], hh, ll);
        h[i] = hh; l[i] = ll;
    }
}

// ---------------- softmax over SEQ, write split bf16 probs ----------------
__global__ __launch_bounds__(256) void softmax_split_k(
    const float* __restrict__ sc, bf16* __restrict__ ah, bf16* __restrict__ al)
{
    __shared__ float row[SEQ];
    __shared__ float red[256];
    const size_t off = (size_t)blockIdx.x * SEQ;
    const int tid = threadIdx.x;

    float mx = -1e30f;
    for (int j = tid; j < SEQ; j += 256) {
        float v = sc[off + j];
        row[j] = v;
        mx = fmaxf(mx, v);
    }
    red[tid] = mx; __syncthreads();
    for (int st = 128; st > 0; st >>= 1) {
        if (tid < st) red[tid] = fmaxf(red[tid], red[tid + st]);
        __syncthreads();
    }
    mx = red[0]; __syncthreads();

    float sum = 0.f;
    for (int j = tid; j < SEQ; j += 256) {
        float e = __expf(row[j] - mx);
        row[j] = e;
        sum += e;
    }
    red[tid] = sum; __syncthreads();
    for (int st = 128; st > 0; st >>= 1) {
        if (tid < st) red[tid] += red[tid + st];
        __syncthreads();
    }
    const float inv = 1.0f / red[0];
    for (int j = tid; j < SEQ; j += 256) {
        bf16 h, l; split_bf(row[j] * inv, h, l);
        ah[off + j] = h; al[off + j] = l;
    }
}

// ---------------- residual + LayerNorm, writes x fp32 and split ----------------
__global__ __launch_bounds__(256) void add_ln_split_k(
    float* __restrict__ x, const float* __restrict__ y,
    const float* __restrict__ g, const float* __restrict__ b,
    bf16* __restrict__ xh, bf16* __restrict__ xl)
{
    __shared__ float r[DM];
    __shared__ float red[256];
    const int tid = threadIdx.x;
    const size_t off = (size_t)blockIdx.x * DM;

    float lsum = 0.f;
    for (int j = tid; j < DM; j += 256) {
        float v = x[off + j] + y[off + j];
        r[j] = v;
        lsum += v;
    }
    red[tid] = lsum; __syncthreads();
    for (int st = 128; st > 0; st >>= 1) {
        if (tid < st) red[tid] += red[tid + st];
        __syncthreads();
    }
    const float mu = red[0] * (1.0f / DM);
    __syncthreads();

    float lv = 0.f;
    for (int j = tid; j < DM; j += 256) {
        float d = r[j] - mu;
        lv += d * d;
    }
    red[tid] = lv; __syncthreads();
    for (int st = 128; st > 0; st >>= 1) {
        if (tid < st) red[tid] += red[tid + st];
        __syncthreads();
    }
    const float rstd = rsqrtf(red[0] * (1.0f / DM) + 1e-5f);

    for (int j = tid; j < DM; j += 256) {
        float v = (r[j] - mu) * rstd * g[j] + b[j];
        x[off + j] = v;
        bf16 h, l; split_bf(v, h, l);
        xh[off + j] = h; xl[off + j] = l;
    }
}

// ---------------- host launch ----------------
static const int SMEM128 = 2 * 128 * 40 * 2 * 2 + 2 * 128 * 40 * 2 * 2; // 81920
static const int SMEM64  = 2 * 128 * 40 * 2 * 2 + 2 * 64 * 40 * 2 * 2;  // 61440

extern "C" void kernel_launch(void* const* d_in, const int* in_sizes, int n_in,
                              void* d_out, int out_size)
{
    const float* x_in = (const float*)d_in[0];
    const float* wq = (const float*)d_in[1];
    const float* bq = (const float*)d_in[2];
    const float* wk = (const float*)d_in[3];
    const float* bk = (const float*)d_in[4];
    const float* wv = (const float*)d_in[5];
    const float* bv = (const float*)d_in[6];
    const float* wo = (const float*)d_in[7];
    const float* bo = (const float*)d_in[8];
    const float* w1 = (const float*)d_in[9];
    const float* b1 = (const float*)d_in[10];
    const float* w2 = (const float*)d_in[11];
    const float* b2 = (const float*)d_in[12];
    const float* ln1g = (const float*)d_in[13];
    const float* ln1b = (const float*)d_in[14];
    const float* ln2g = (const float*)d_in[15];
    const float* ln2b = (const float*)d_in[16];

    float* x = (float*)d_out;

    bf16 *wqTh, *wqTl, *wkTh, *wkTl, *wvTh, *wvTl, *woTh, *woTl;
    bf16 *w1Th, *w1Tl, *w2Th, *w2Tl;
    bf16 *xh, *xl, *qh, *ql, *kh, *kl, *vh, *vl, *vth, *vtl, *ch, *cl, *hh, *hl, *ah, *al;
    float *sc, *tmp;
    cudaGetSymbolAddress((void**)&wqTh, g_wqT_h); cudaGetSymbolAddress((void**)&wqTl, g_wqT_l);
    cudaGetSymbolAddress((void**)&wkTh, g_wkT_h); cudaGetSymbolAddress((void**)&wkTl, g_wkT_l);
    cudaGetSymbolAddress((void**)&wvTh, g_wvT_h); cudaGetSymbolAddress((void**)&wvTl, g_wvT_l);
    cudaGetSymbolAddress((void**)&woTh, g_woT_h); cudaGetSymbolAddress((void**)&woTl, g_woT_l);
    cudaGetSymbolAddress((void**)&w1Th, g_w1T_h); cudaGetSymbolAddress((void**)&w1Tl, g_w1T_l);
    cudaGetSymbolAddress((void**)&w2Th, g_w2T_h); cudaGetSymbolAddress((void**)&w2Tl, g_w2T_l);
    cudaGetSymbolAddress((void**)&xh, g_xh); cudaGetSymbolAddress((void**)&xl, g_xl);
    cudaGetSymbolAddress((void**)&qh, g_qh); cudaGetSymbolAddress((void**)&ql, g_ql);
    cudaGetSymbolAddress((void**)&kh, g_kh); cudaGetSymbolAddress((void**)&kl, g_kl);
    cudaGetSymbolAddress((void**)&vh, g_vh); cudaGetSymbolAddress((void**)&vl, g_vl);
    cudaGetSymbolAddress((void**)&vth, g_vth); cudaGetSymbolAddress((void**)&vtl, g_vtl);
    cudaGetSymbolAddress((void**)&ch, g_ch); cudaGetSymbolAddress((void**)&cl, g_cl);
    cudaGetSymbolAddress((void**)&hh, g_hh); cudaGetSymbolAddress((void**)&hl, g_hl);
    cudaGetSymbolAddress((void**)&ah, g_ah); cudaGetSymbolAddress((void**)&al, g_al);
    cudaGetSymbolAddress((void**)&sc, g_sc); cudaGetSymbolAddress((void**)&tmp, g_tmp);

    cudaFuncSetAttribute(mmsync<128, 0>, cudaFuncAttributeMaxDynamicSharedMemorySize, SMEM128);
    cudaFuncSetAttribute(mmsync<128, 1>, cudaFuncAttributeMaxDynamicSharedMemorySize, SMEM128);
    cudaFuncSetAttribute(mmsync<128, 2>, cudaFuncAttributeMaxDynamicSharedMemorySize, SMEM128);
    cudaFuncSetAttribute(mmsync<128, 4>, cudaFuncAttributeMaxDynamicSharedMemorySize, SMEM128);
    cudaFuncSetAttribute(mmsync<64, 3>,  cudaFuncAttributeMaxDynamicSharedMemorySize, SMEM64);

    const dim3 tb(32, 8);
    trans_split_k<<<dim3(DM / 32, DM / 32, NL), tb>>>(wq, wqTh, wqTl, DM, DM);
    trans_split_k<<<dim3(DM / 32, DM / 32, NL), tb>>>(wk, wkTh, wkTl, DM, DM);
    trans_split_k<<<dim3(DM / 32, DM / 32, NL), tb>>>(wv, wvTh, wvTl, DM, DM);
    trans_split_k<<<dim3(DM / 32, DM / 32, NL), tb>>>(wo, woTh, woTl, DM, DM);
    trans_split_k<<<dim3(DFF / 32, DM / 32, NL), tb>>>(w1, w1Th, w1Tl, DM, DFF);
    trans_split_k<<<dim3(DM / 32, DFF / 32, NL), tb>>>(w2, w2Th, w2Tl, DFF, DM);

    cudaMemcpyAsync(x, x_in, (size_t)SEQ * DM * sizeof(float), cudaMemcpyDeviceToDevice);
    split_k<<<(SEQ * DM) / 256, 256>>>(x_in, xh, xl, SEQ * DM);

    const dim3 gP(DM / 128, SEQ / 128);       // (8,16)
    const dim3 gS(SEQ / 128, SEQ / 128, NH);  // (16,16,16)
    const dim3 gAV(1, SEQ / 128, NH);         // (1,16,16)
    const dim3 gF1(DFF / 128, SEQ / 128);     // (32,16)

    for (int l = 0; l < NL; l++) {
        const size_t lW = (size_t)l * DM * DM;
        const size_t lF = (size_t)l * DM * DFF;

        mmsync<128, 2><<<gP, 256, SMEM128>>>(xh, xl, wqTh + lW, wqTl + lW, bq + l * DM,
            nullptr, qh, ql, DM, DM, DM, DM, 0, 0, 0, 1.f);
        mmsync<128, 2><<<gP, 256, SMEM128>>>(xh, xl, wkTh + lW, wkTl + lW, bk + l * DM,
            nullptr, kh, kl, DM, DM, DM, DM, 0, 0, 0, 1.f);
        mmsync<128, 2><<<gP, 256, SMEM128>>>(xh, xl, wvTh + lW, wvTl + lW, bv + l * DM,
            nullptr, vh, vl, DM, DM, DM, DM, 0, 0, 0, 1.f);
        trans2_bf16_k<<<dim3(DM / 32, SEQ / 32), tb>>>(vh, vth, vl, vtl, SEQ, DM);

        // scores[h] = (Q_h @ K_h^T)/8 (fp32)
        mmsync<128, 0><<<gS, 256, SMEM128>>>(qh, ql, kh, kl, nullptr,
            sc, nullptr, nullptr, DK, DM, DM, SEQ,
            64, 64, (long long)SEQ * SEQ, 0.125f);

        softmax_split_k<<<NH * SEQ, 256>>>(sc, ah, al);

        // ctx[h] = attn[h] @ V_h
        mmsync<64, 3><<<gAV, 256, SMEM64>>>(ah, al, vth, vtl, nullptr,
            nullptr, ch, cl, SEQ, SEQ, SEQ, DM,
            (long long)SEQ * SEQ, (long long)64 * SEQ, 64, 1.f);

        mmsync<128, 1><<<gP, 256, SMEM128>>>(ch, cl, woTh + lW, woTl + lW, bo + l * DM,
            tmp, nullptr, nullptr, DM, DM, DM, DM, 0, 0, 0, 1.f);

        add_ln_split_k<<<SEQ, 256>>>(x, tmp, ln1g + l * DM, ln1b + l * DM, xh, xl);

        mmsync<128, 4><<<gF1, 256, SMEM128>>>(xh, xl, w1Th + lF, w1Tl + lF, b1 + l * DFF,
            nullptr, hh, hl, DM, DM, DM, DFF, 0, 0, 0, 1.f);

        mmsync<128, 1><<<gP, 256, SMEM128>>>(hh, hl, w2Th + lF, w2Tl + lF, b2 + l * DM,
            tmp, nullptr, nullptr, DFF, DFF, DFF, DM, 0, 0, 0, 1.f);

        add_ln_split_k<<<SEQ, 256>>>(x, tmp, ln2g + l * DM, ln2b + l * DM, xh, xl);
    }
}

// round 7
// speedup vs baseline: 2.9540x; 1.3075x over previous
#include <cuda_runtime.h>
#include <cuda_bf16.h>
#include <math.h>
#include <stdint.h>

#define SEQ 2048
#define DM  1024
#define NH  16
#define DK  64
#define DFF 4096
#define NL  4

typedef __nv_bfloat16 bf16;

// ---------------- device scratch (no cudaMalloc allowed) ----------------
__device__ bf16 g_wqT_h[NL * DM * DM], g_wqT_l[NL * DM * DM];
__device__ bf16 g_wkT_h[NL * DM * DM], g_wkT_l[NL * DM * DM];
__device__ bf16 g_wvT_h[NL * DM * DM], g_wvT_l[NL * DM * DM];
__device__ bf16 g_woT_h[NL * DM * DM], g_woT_l[NL * DM * DM];
__device__ bf16 g_w1T_h[NL * DM * DFF], g_w1T_l[NL * DM * DFF];
__device__ bf16 g_w2T_h[NL * DM * DFF], g_w2T_l[NL * DM * DFF];
__device__ bf16 g_xh[SEQ * DM], g_xl[SEQ * DM];
__device__ bf16 g_qh[SEQ * DM], g_ql[SEQ * DM];
__device__ bf16 g_kh[SEQ * DM], g_kl[SEQ * DM];
__device__ bf16 g_vh[SEQ * DM], g_vl[SEQ * DM];
__device__ bf16 g_vth[DM * SEQ], g_vtl[DM * SEQ];   // V^T
__device__ bf16 g_ch[SEQ * DM], g_cl[SEQ * DM];
__device__ bf16 g_hh[SEQ * DFF], g_hl[SEQ * DFF];
__device__ float g_tmp[SEQ * DM];

// ---------------- small helpers ----------------
__device__ __forceinline__ float gelu_f(float v) {
    return 0.5f * v * (1.0f + tanhf(0.7978845608028654f * (v + 0.044715f * v * v * v)));
}
__device__ __forceinline__ void split_bf(float v, bf16& h, bf16& l) {
    h = __float2bfloat16(v);
    l = __float2bfloat16(v - __bfloat162float(h));
}
__device__ __forceinline__ void cpa16(uint32_t dst, const void* src) {
    asm volatile("cp.async.cg.shared.global [%0], [%1], 16;" :: "r"(dst), "l"(src));
}
#define CP_COMMIT() asm volatile("cp.async.commit_group;" ::: "memory")
#define CP_WAIT0()  asm volatile("cp.async.wait_group 0;" ::: "memory")
#define CP_WAIT1()  asm volatile("cp.async.wait_group 1;" ::: "memory")
#define LDSM4(r, a) asm volatile( \
    "ldmatrix.sync.aligned.m8n8.x4.shared.b16 {%0,%1,%2,%3}, [%4];" \
    : "=r"((r)[0]), "=r"((r)[1]), "=r"((r)[2]), "=r"((r)[3]) : "r"(a))

__device__ __forceinline__ void mma16816(float* c, const uint32_t* a, const uint32_t* b) {
    asm volatile(
        "mma.sync.aligned.m16n8k16.row.col.f32.bf16.bf16.f32 "
        "{%0,%1,%2,%3}, {%4,%5,%6,%7}, {%8,%9}, {%0,%1,%2,%3};"
        : "+f"(c[0]), "+f"(c[1]), "+f"(c[2]), "+f"(c[3])
        : "r"(a[0]), "r"(a[1]), "r"(a[2]), "r"(a[3]), "r"(b[0]), "r"(b[1]));
}
__device__ __forceinline__ uint32_t sm_addr(const void* p) {
    return (uint32_t)__cvta_generic_to_shared(p);
}
__device__ __forceinline__ void pack_split2(float x, float y, uint32_t& h, uint32_t& l) {
    __nv_bfloat162 hh, ll;
    hh.x = __float2bfloat16(x); ll.x = __float2bfloat16(x - __bfloat162float(hh.x));
    hh.y = __float2bfloat16(y); ll.y = __float2bfloat16(y - __bfloat162float(hh.y));
    h = *(uint32_t*)&hh; l = *(uint32_t*)&ll;
}

// ---------------- mma.sync GEMM, bf16x3 split, fp32 accum ----------------
// D[128, BN] tile of scale*(A @ B^T) [+bias][gelu]; A,B split hi/lo, K-contiguous.
// EPI: 1 f32+bias, 2 split+bias, 4 gelu(v+bias) split
template <int BN, int EPI>
__global__ __launch_bounds__(256) void mmsync(
    const bf16* __restrict__ Ah, const bf16* __restrict__ Al,
    const bf16* __restrict__ Bh, const bf16* __restrict__ Bl,
    const float* __restrict__ bias,
    float* __restrict__ Cf, bf16* __restrict__ Ch, bf16* __restrict__ Cl,
    int K, int lda, int ldb, int ldc)
{
    constexpr int WGN = 4;                     // warps along N
    constexpr int WM  = 64;                    // warp tile M
    constexpr int MF  = WM / 16;
    constexpr int NF  = 4;                     // warp tile N = 32
    constexpr int SP  = 40;                    // padded row stride (halfs)

    extern __shared__ bf16 sm[];
    bf16* sAH = sm;
    bf16* sAL = sAH + 2 * 128 * SP;
    bf16* sBH = sAL + 2 * 128 * SP;
    bf16* sBL = sBH + 2 * BN * SP;

    const int tid = threadIdx.x;
    const int wid = tid >> 5;
    const int lane = tid & 31;
    const int gid = lane >> 2, tig = lane & 3;
    const int bm = blockIdx.y * 128;
    const int bn = blockIdx.x * BN;

    const int wm0 = (wid / WGN) * WM;
    const int wn0 = (wid % WGN) * 32;

    float acc[MF][NF][4];
#pragma unroll
    for (int i = 0; i < MF; i++)
#pragma unroll
        for (int j = 0; j < NF; j++)
#pragma unroll
            for (int q = 0; q < 4; q++) acc[i][j][q] = 0.f;

    const int nk = K >> 5;

    auto loadStage = [&](int st, int k0) {
#pragma unroll
        for (int i = 0; i < 2; i++) {
            int ch = tid + i * 256;
            int row = ch >> 2, c = ch & 3;
            size_t g = (size_t)(bm + row) * lda + k0 + c * 8;
            int so = st * 128 * SP + row * SP + c * 8;
            cpa16(sm_addr(&sAH[so]), Ah + g);
            cpa16(sm_addr(&sAL[so]), Al + g);
        }
#pragma unroll
        for (int i = 0; i < BN / 64; i++) {
            int ch = tid + i * 256;
            int row = ch >> 2, c = ch & 3;
            size_t g = (size_t)(bn + row) * ldb + k0 + c * 8;
            int so = st * BN * SP + row * SP + c * 8;
            cpa16(sm_addr(&sBH[so]), Bh + g);
            cpa16(sm_addr(&sBL[so]), Bl + g);
        }
    };

    loadStage(0, 0);
    CP_COMMIT();

    for (int kt = 0; kt < nk; kt++) {
        if (kt + 1 < nk) {
            loadStage((kt + 1) & 1, (kt + 1) << 5);
            CP_COMMIT();
            CP_WAIT1();
        } else {
            CP_WAIT0();
        }
        __syncthreads();

        const int st = kt & 1;
        const bf16* aH = sAH + st * 128 * SP;
        const bf16* aL = sAL + st * 128 * SP;
        const bf16* bH = sBH + st * BN * SP;
        const bf16* bL = sBL + st * BN * SP;

#pragma unroll
        for (int kk = 0; kk < 2; kk++) {
            const int koff = kk * 16;
            uint32_t ah[MF][4], al[MF][4];
            const int ar = (lane & 15);
            const int ac = koff + ((lane >> 4) << 3);
#pragma unroll
            for (int mf = 0; mf < MF; mf++) {
                int r = wm0 + mf * 16 + ar;
                LDSM4(ah[mf], sm_addr(&aH[r * SP + ac]));
                LDSM4(al[mf], sm_addr(&aL[r * SP + ac]));
            }
            uint32_t bh[NF][2], bl[NF][2];
            const int br = (lane < 16) ? (lane & 7) : 8 + (lane & 7);
            const int bc = koff + (((lane >> 3) & 1) << 3);
#pragma unroll
            for (int nn = 0; nn < NF; nn += 2) {
                int r = wn0 + nn * 8 + br;
                uint32_t t[4];
                LDSM4(t, sm_addr(&bH[r * SP + bc]));
                bh[nn][0] = t[0]; bh[nn][1] = t[1];
                bh[nn + 1][0] = t[2]; bh[nn + 1][1] = t[3];
                LDSM4(t, sm_addr(&bL[r * SP + bc]));
                bl[nn][0] = t[0]; bl[nn][1] = t[1];
                bl[nn + 1][0] = t[2]; bl[nn + 1][1] = t[3];
            }
#pragma unroll
            for (int mf = 0; mf < MF; mf++)
#pragma unroll
                for (int nf = 0; nf < NF; nf++) {
                    mma16816(acc[mf][nf], ah[mf], bh[nf]);
                    mma16816(acc[mf][nf], ah[mf], bl[nf]);
                    mma16816(acc[mf][nf], al[mf], bh[nf]);
                }
        }
        __syncthreads();
    }

    // ---------------- epilogue ----------------
#pragma unroll
    for (int mf = 0; mf < MF; mf++) {
        const int mA = bm + wm0 + mf * 16 + gid;
        const int mB = mA + 8;
#pragma unroll
        for (int nf = 0; nf < NF; nf++) {
            const int n = bn + wn0 + nf * 8 + 2 * tig;
            float c0 = acc[mf][nf][0], c1 = acc[mf][nf][1];
            float c2 = acc[mf][nf][2], c3 = acc[mf][nf][3];
            if (EPI == 1) {
                float b0 = bias[n], b1 = bias[n + 1];
                float2 u = make_float2(c0 + b0, c1 + b1);
                float2 w = make_float2(c2 + b0, c3 + b1);
                *(float2*)(Cf + (size_t)mA * ldc + n) = u;
                *(float2*)(Cf + (size_t)mB * ldc + n) = w;
            } else {
                float b0 = bias[n], b1 = bias[n + 1];
                float v0 = c0 + b0, v1 = c1 + b1, v2 = c2 + b0, v3 = c3 + b1;
                if (EPI == 4) {
                    v0 = gelu_f(v0); v1 = gelu_f(v1);
                    v2 = gelu_f(v2); v3 = gelu_f(v3);
                }
                uint32_t h01, l01, h23, l23;
                pack_split2(v0, v1, h01, l01);
                pack_split2(v2, v3, h23, l23);
                *(uint32_t*)(Ch + (size_t)mA * ldc + n) = h01;
                *(uint32_t*)(Cl + (size_t)mA * ldc + n) = l01;
                *(uint32_t*)(Ch + (size_t)mB * ldc + n) = h23;
                *(uint32_t*)(Cl + (size_t)mB * ldc + n) = l23;
            }
        }
    }
}

// ---------------- flash attention: S=QK^T/8, online softmax, O=PV ----------------
// grid (NH, SEQ/128), 256 threads (8 warps x 16 q-rows)
__global__ __launch_bounds__(256) void flash_attn(
    const bf16* __restrict__ qh_g, const bf16* __restrict__ ql_g,
    const bf16* __restrict__ kh_g, const bf16* __restrict__ kl_g,
    const bf16* __restrict__ vth_g, const bf16* __restrict__ vtl_g,
    bf16* __restrict__ ch_g, bf16* __restrict__ cl_g)
{
    constexpr int KSP = 72, VSP = 136;
    const int h = blockIdx.x;
    const int q0 = blockIdx.y * 128;
    const int tid = threadIdx.x, wid = tid >> 5, lane = tid & 31;
    const int gid = lane >> 2, tig = lane & 3;

    extern __shared__ bf16 sm[];
    bf16* sKH = sm;                       // 2 * 128*72
    bf16* sKL = sKH + 2 * 128 * KSP;
    bf16* sVH = sKL + 2 * 128 * KSP;      // 2 * 64*136
    bf16* sVL = sVH + 2 * 64 * VSP;

    // ---- prologue: Q tile into stage-0 K buffers, extract frags ----
#pragma unroll
    for (int i = 0; i < 4; i++) {
        int ch = tid + i * 256;
        int row = ch >> 3, c = ch & 7;
        size_t g = (size_t)(q0 + row) * DM + h * 64 + c * 8;
        cpa16(sm_addr(&sKH[row * KSP + c * 8]), qh_g + g);
        cpa16(sm_addr(&sKL[row * KSP + c * 8]), ql_g + g);
    }
    CP_COMMIT(); CP_WAIT0();
    __syncthreads();

    uint32_t qfh[4][4], qfl[4][4];
    {
        const int ar = lane & 15, acb = (lane >> 4) << 3;
#pragma unroll
        for (int kf = 0; kf < 4; kf++) {
            int off = (wid * 16 + ar) * KSP + kf * 16 + acb;
            LDSM4(qfh[kf], sm_addr(&sKH[off]));
            LDSM4(qfl[kf], sm_addr(&sKL[off]));
        }
    }
    __syncthreads();

    float oacc[8][4];
#pragma unroll
    for (int i = 0; i < 8; i++)
#pragma unroll
        for (int q = 0; q < 4; q++) oacc[i][q] = 0.f;
    float m0 = -1e30f, m1 = -1e30f, l0 = 0.f, l1 = 0.f;

    auto loadKV = [&](int st, int s0) {
#pragma unroll
        for (int i = 0; i < 4; i++) {
            int ch = tid + i * 256;
            int row = ch >> 3, c = ch & 7;
            size_t g = (size_t)(s0 + row) * DM + h * 64 + c * 8;
            int so = st * 128 * KSP + row * KSP + c * 8;
            cpa16(sm_addr(&sKH[so]), kh_g + g);
            cpa16(sm_addr(&sKL[so]), kl_g + g);
        }
#pragma unroll
        for (int i = 0; i < 4; i++) {
            int ch = tid + i * 256;
            int row = ch >> 4, c = ch & 15;
            size_t g = (size_t)(h * 64 + row) * SEQ + s0 + c * 8;
            int so = st * 64 * VSP + row * VSP + c * 8;
            cpa16(sm_addr(&sVH[so]), vth_g + g);
            cpa16(sm_addr(&sVL[so]), vtl_g + g);
        }
    };

    loadKV(0, 0);
    CP_COMMIT();

    const int br = (lane < 16) ? (lane & 7) : 8 + (lane & 7);
    const int bcsel = ((lane >> 3) & 1) << 3;

    for (int kt = 0; kt < SEQ / 128; kt++) {
        if (kt + 1 < SEQ / 128) {
            loadKV((kt + 1) & 1, (kt + 1) * 128);
            CP_COMMIT();
            CP_WAIT1();
        } else {
            CP_WAIT0();
        }
        __syncthreads();

        const int st = kt & 1;
        const bf16* kH = sKH + st * 128 * KSP;
        const bf16* kL = sKL + st * 128 * KSP;
        const bf16* vH = sVH + st * 64 * VSP;
        const bf16* vL = sVL + st * 64 * VSP;

        float sacc[16][4];
#pragma unroll
        for (int i = 0; i < 16; i++)
#pragma unroll
            for (int q = 0; q < 4; q++) sacc[i][q] = 0.f;

#pragma unroll
        for (int kf = 0; kf < 4; kf++) {
            const int bc = kf * 16 + bcsel;
#pragma unroll
            for (int nn = 0; nn < 16; nn += 2) {
                uint32_t th[4], tl[4];
                LDSM4(th, sm_addr(&kH[(nn * 8 + br) * KSP + bc]));
                LDSM4(tl, sm_addr(&kL[(nn * 8 + br) * KSP + bc]));
                mma16816(sacc[nn], qfh[kf], th);
                mma16816(sacc[nn], qfh[kf], tl);
                mma16816(sacc[nn], qfl[kf], th);
                mma16816(sacc[nn + 1], qfh[kf], th + 2);
                mma16816(sacc[nn + 1], qfh[kf], tl + 2);
                mma16816(sacc[nn + 1], qfl[kf], th + 2);
            }
        }

        // scale + row max (rows gid / gid+8 of this warp's strip)
        float tm0 = -1e30f, tm1 = -1e30f;
#pragma unroll
        for (int nf = 0; nf < 16; nf++) {
            sacc[nf][0] *= 0.125f; sacc[nf][1] *= 0.125f;
            sacc[nf][2] *= 0.125f; sacc[nf][3] *= 0.125f;
            tm0 = fmaxf(tm0, fmaxf(sacc[nf][0], sacc[nf][1]));
            tm1 = fmaxf(tm1, fmaxf(sacc[nf][2], sacc[nf][3]));
        }
        tm0 = fmaxf(tm0, __shfl_xor_sync(0xffffffffu, tm0, 1));
        tm0 = fmaxf(tm0, __shfl_xor_sync(0xffffffffu, tm0, 2));
        tm1 = fmaxf(tm1, __shfl_xor_sync(0xffffffffu, tm1, 1));
        tm1 = fmaxf(tm1, __shfl_xor_sync(0xffffffffu, tm1, 2));

        const float mn0 = fmaxf(m0, tm0), mn1 = fmaxf(m1, tm1);
        const float a0 = __expf(m0 - mn0), a1 = __expf(m1 - mn1);

        float rs0 = 0.f, rs1 = 0.f;
#pragma unroll
        for (int nf = 0; nf < 16; nf++) {
            sacc[nf][0] = __expf(sacc[nf][0] - mn0);
            sacc[nf][1] = __expf(sacc[nf][1] - mn0);
            sacc[nf][2] = __expf(sacc[nf][2] - mn1);
            sacc[nf][3] = __expf(sacc[nf][3] - mn1);
            rs0 += sacc[nf][0] + sacc[nf][1];
            rs1 += sacc[nf][2] + sacc[nf][3];
        }
        rs0 += __shfl_xor_sync(0xffffffffu, rs0, 1);
        rs0 += __shfl_xor_sync(0xffffffffu, rs0, 2);
        rs1 += __shfl_xor_sync(0xffffffffu, rs1, 1);
        rs1 += __shfl_xor_sync(0xffffffffu, rs1, 2);

        m0 = mn0; m1 = mn1;
        l0 = l0 * a0 + rs0;
        l1 = l1 * a1 + rs1;

#pragma unroll
        for (int nf = 0; nf < 8; nf++) {
            oacc[nf][0] *= a0; oacc[nf][1] *= a0;
            oacc[nf][2] *= a1; oacc[nf][3] *= a1;
        }

        // O += P @ V   (P from sacc regs, V^T from smem)
#pragma unroll
        for (int j = 0; j < 8; j++) {
            uint32_t pah[4], pal[4];
            pack_split2(sacc[2 * j][0], sacc[2 * j][1], pah[0], pal[0]);
            pack_split2(sacc[2 * j][2], sacc[2 * j][3], pah[1], pal[1]);
            pack_split2(sacc[2 * j + 1][0], sacc[2 * j + 1][1], pah[2], pal[2]);
            pack_split2(sacc[2 * j + 1][2], sacc[2 * j + 1][3], pah[3], pal[3]);
            const int bc = j * 16 + bcsel;
#pragma unroll
            for (int nn = 0; nn < 8; nn += 2) {
                uint32_t th[4], tl[4];
                LDSM4(th, sm_addr(&vH[(nn * 8 + br) * VSP + bc]));
                LDSM4(tl, sm_addr(&vL[(nn * 8 + br) * VSP + bc]));
                mma16816(oacc[nn], pah, th);
                mma16816(oacc[nn], pah, tl);
                mma16816(oacc[nn], pal, th);
                mma16816(oacc[nn + 1], pah, th + 2);
                mma16816(oacc[nn + 1], pah, tl + 2);
                mma16816(oacc[nn + 1], pal, th + 2);
            }
        }
        __syncthreads();
    }

    // ---- epilogue: O/l, split, store ctx ----
    const float il0 = 1.f / l0, il1 = 1.f / l1;
    const int mA = q0 + wid * 16 + gid;
    const int mB = mA + 8;
#pragma unroll
    for (int nf = 0; nf < 8; nf++) {
        const int col = h * 64 + nf * 8 + 2 * tig;
        uint32_t h01, l01, h23, l23;
        pack_split2(oacc[nf][0] * il0, oacc[nf][1] * il0, h01, l01);
        pack_split2(oacc[nf][2] * il1, oacc[nf][3] * il1, h23, l23);
        *(uint32_t*)(ch_g + (size_t)mA * DM + col) = h01;
        *(uint32_t*)(cl_g + (size_t)mA * DM + col) = l01;
        *(uint32_t*)(ch_g + (size_t)mB * DM + col) = h23;
        *(uint32_t*)(cl_g + (size_t)mB * DM + col) = l23;
    }
}

// ---------------- transpose + split weights: W[R,C] fp32 -> WT[C,R] bf16 hi/lo ----------------
__global__ void trans_split_k(const float* __restrict__ in, bf16* __restrict__ oh,
                              bf16* __restrict__ ol, int R, int C)
{
    __shared__ float t[32][33];
    const size_t zo = (size_t)blockIdx.z * R * C;
    in += zo; oh += zo; ol += zo;
    const int r0 = blockIdx.y * 32, c0 = blockIdx.x * 32;
    const int tx = threadIdx.x, ty = threadIdx.y;
#pragma unroll
    for (int i = 0; i < 32; i += 8)
        t[ty + i][tx] = in[(size_t)(r0 + ty + i) * C + c0 + tx];
    __syncthreads();
#pragma unroll
    for (int i = 0; i < 32; i += 8) {
        float v = t[tx][ty + i];
        bf16 h, l; split_bf(v, h, l);
        size_t o = (size_t)(c0 + ty + i) * R + r0 + tx;
        oh[o] = h; ol[o] = l;
    }
}

// ---------------- transpose two bf16 matrices [R,C] -> [C,R] ----------------
__global__ void trans2_bf16_k(const bf16* __restrict__ a, bf16* __restrict__ at,
                              const bf16* __restrict__ b, bf16* __restrict__ bt,
                              int R, int C)
{
    __shared__ bf16 ta[32][33], tb[32][33];
    const int r0 = blockIdx.y * 32, c0 = blockIdx.x * 32;
    const int tx = threadIdx.x, ty = threadIdx.y;
#pragma unroll
    for (int i = 0; i < 32; i += 8) {
        size_t g = (size_t)(r0 + ty + i) * C + c0 + tx;
        ta[ty + i][tx] = a[g];
        tb[ty + i][tx] = b[g];
    }
    __syncthreads();
#pragma unroll
    for (int i = 0; i < 32; i += 8) {
        size_t o = (size_t)(c0 + ty + i) * R + r0 + tx;
        at[o] = ta[tx][ty + i];
        bt[o] = tb[tx][ty + i];
    }
}

// ---------------- elementwise split ----------------
__global__ void split_k(const float* __restrict__ x, bf16* __restrict__ h,
                        bf16* __restrict__ l, int n)
{
    int i = blockIdx.x * 256 + threadIdx.x;
    if (i < n) {
        bf16 hh, ll; split_bf(x[i], hh, ll);
        h[i] = hh; l[i] = ll;
    }
}

// ---------------- residual + LayerNorm, writes x fp32 and split ----------------
__global__ __launch_bounds__(256) void add_ln_split_k(
    float* __restrict__ x, const float* __restrict__ y,
    const float* __restrict__ g, const float* __restrict__ b,
    bf16* __restrict__ xh, bf16* __restrict__ xl)
{
    __shared__ float r[DM];
    __shared__ float red[256];
    const int tid = threadIdx.x;
    const size_t off = (size_t)blockIdx.x * DM;

    float lsum = 0.f;
    for (int j = tid; j < DM; j += 256) {
        float v = x[off + j] + y[off + j];
        r[j] = v;
        lsum += v;
    }
    red[tid] = lsum; __syncthreads();
    for (int st = 128; st > 0; st >>= 1) {
        if (tid < st) red[tid] += red[tid + st];
        __syncthreads();
    }
    const float mu = red[0] * (1.0f / DM);
    __syncthreads();

    float lv = 0.f;
    for (int j = tid; j < DM; j += 256) {
        float d = r[j] - mu;
        lv += d * d;
    }
    red[tid] = lv; __syncthreads();
    for (int st = 128; st > 0; st >>= 1) {
        if (tid < st) red[tid] += red[tid + st];
        __syncthreads();
    }
    const float rstd = rsqrtf(red[0] * (1.0f / DM) + 1e-5f);

    for (int j = tid; j < DM; j += 256) {
        float v = (r[j] - mu) * rstd * g[j] + b[j];
        x[off + j] = v;
        bf16 h, l; split_bf(v, h, l);
        xh[off + j] = h; xl[off + j] = l;
    }
}

// ---------------- host launch ----------------
static const int SMEM128 = 81920;  // mmsync BN=128
static const int SMEMFA  = (2 * 128 * 72 + 2 * 128 * 72 + 2 * 64 * 136 + 2 * 64 * 136) * 2; // 143360

extern "C" void kernel_launch(void* const* d_in, const int* in_sizes, int n_in,
                              void* d_out, int out_size)
{
    const float* x_in = (const float*)d_in[0];
    const float* wq = (const float*)d_in[1];
    const float* bq = (const float*)d_in[2];
    const float* wk = (const float*)d_in[3];
    const float* bk = (const float*)d_in[4];
    const float* wv = (const float*)d_in[5];
    const float* bv = (const float*)d_in[6];
    const float* wo = (const float*)d_in[7];
    const float* bo = (const float*)d_in[8];
    const float* w1 = (const float*)d_in[9];
    const float* b1 = (const float*)d_in[10];
    const float* w2 = (const float*)d_in[11];
    const float* b2 = (const float*)d_in[12];
    const float* ln1g = (const float*)d_in[13];
    const float* ln1b = (const float*)d_in[14];
    const float* ln2g = (const float*)d_in[15];
    const float* ln2b = (const float*)d_in[16];

    float* x = (float*)d_out;

    bf16 *wqTh, *wqTl, *wkTh, *wkTl, *wvTh, *wvTl, *woTh, *woTl;
    bf16 *w1Th, *w1Tl, *w2Th, *w2Tl;
    bf16 *xh, *xl, *qh, *ql, *kh, *kl, *vh, *vl, *vth, *vtl, *ch, *cl, *hh, *hl;
    float *tmp;
    cudaGetSymbolAddress((void**)&wqTh, g_wqT_h); cudaGetSymbolAddress((void**)&wqTl, g_wqT_l);
    cudaGetSymbolAddress((void**)&wkTh, g_wkT_h); cudaGetSymbolAddress((void**)&wkTl, g_wkT_l);
    cudaGetSymbolAddress((void**)&wvTh, g_wvT_h); cudaGetSymbolAddress((void**)&wvTl, g_wvT_l);
    cudaGetSymbolAddress((void**)&woTh, g_woT_h); cudaGetSymbolAddress((void**)&woTl, g_woT_l);
    cudaGetSymbolAddress((void**)&w1Th, g_w1T_h); cudaGetSymbolAddress((void**)&w1Tl, g_w1T_l);
    cudaGetSymbolAddress((void**)&w2Th, g_w2T_h); cudaGetSymbolAddress((void**)&w2Tl, g_w2T_l);
    cudaGetSymbolAddress((void**)&xh, g_xh); cudaGetSymbolAddress((void**)&xl, g_xl);
    cudaGetSymbolAddress((void**)&qh, g_qh); cudaGetSymbolAddress((void**)&ql, g_ql);
    cudaGetSymbolAddress((void**)&kh, g_kh); cudaGetSymbolAddress((void**)&kl, g_kl);
    cudaGetSymbolAddress((void**)&vh, g_vh); cudaGetSymbolAddress((void**)&vl, g_vl);
    cudaGetSymbolAddress((void**)&vth, g_vth); cudaGetSymbolAddress((void**)&vtl, g_vtl);
    cudaGetSymbolAddress((void**)&ch, g_ch); cudaGetSymbolAddress((void**)&cl, g_cl);
    cudaGetSymbolAddress((void**)&hh, g_hh); cudaGetSymbolAddress((void**)&hl, g_hl);
    cudaGetSymbolAddress((void**)&tmp, g_tmp);

    cudaFuncSetAttribute(mmsync<128, 1>, cudaFuncAttributeMaxDynamicSharedMemorySize, SMEM128);
    cudaFuncSetAttribute(mmsync<128, 2>, cudaFuncAttributeMaxDynamicSharedMemorySize, SMEM128);
    cudaFuncSetAttribute(mmsync<128, 4>, cudaFuncAttributeMaxDynamicSharedMemorySize, SMEM128);
    cudaFuncSetAttribute(flash_attn, cudaFuncAttributeMaxDynamicSharedMemorySize, SMEMFA);

    const dim3 tb(32, 8);
    trans_split_k<<<dim3(DM / 32, DM / 32, NL), tb>>>(wq, wqTh, wqTl, DM, DM);
    trans_split_k<<<dim3(DM / 32, DM / 32, NL), tb>>>(wk, wkTh, wkTl, DM, DM);
    trans_split_k<<<dim3(DM / 32, DM / 32, NL), tb>>>(wv, wvTh, wvTl, DM, DM);
    trans_split_k<<<dim3(DM / 32, DM / 32, NL), tb>>>(wo, woTh, woTl, DM, DM);
    trans_split_k<<<dim3(DFF / 32, DM / 32, NL), tb>>>(w1, w1Th, w1Tl, DM, DFF);
    trans_split_k<<<dim3(DM / 32, DFF / 32, NL), tb>>>(w2, w2Th, w2Tl, DFF, DM);

    cudaMemcpyAsync(x, x_in, (size_t)SEQ * DM * sizeof(float), cudaMemcpyDeviceToDevice);
    split_k<<<(SEQ * DM) / 256, 256>>>(x_in, xh, xl, SEQ * DM);

    const dim3 gP(DM / 128, SEQ / 128);       // (8,16)
    const dim3 gFA(NH, SEQ / 128);            // (16,16)
    const dim3 gF1(DFF / 128, SEQ / 128);     // (32,16)

    for (int l = 0; l < NL; l++) {
        const size_t lW = (size_t)l * DM * DM;
        const size_t lF = (size_t)l * DM * DFF;

        mmsync<128, 2><<<gP, 256, SMEM128>>>(xh, xl, wqTh + lW, wqTl + lW, bq + l * DM,
            nullptr, qh, ql, DM, DM, DM, DM);
        mmsync<128, 2><<<gP, 256, SMEM128>>>(xh, xl, wkTh + lW, wkTl + lW, bk + l * DM,
            nullptr, kh, kl, DM, DM, DM, DM);
        mmsync<128, 2><<<gP, 256, SMEM128>>>(xh, xl, wvTh + lW, wvTl + lW, bv + l * DM,
            nullptr, vh, vl, DM, DM, DM, DM);
        trans2_bf16_k<<<dim3(DM / 32, SEQ / 32), tb>>>(vh, vth, vl, vtl, SEQ, DM);

        // fused attention: scores + softmax + AV
        flash_attn<<<gFA, 256, SMEMFA>>>(qh, ql, kh, kl, vth, vtl, ch, cl);

        mmsync<128, 1><<<gP, 256, SMEM128>>>(ch, cl, woTh + lW, woTl + lW, bo + l * DM,
            tmp, nullptr, nullptr, DM, DM, DM, DM);

        add_ln_split_k<<<SEQ, 256>>>(x, tmp, ln1g + l * DM, ln1b + l * DM, xh, xl);

        mmsync<128, 4><<<gF1, 256, SMEM128>>>(xh, xl, w1Th + lF, w1Tl + lF, b1 + l * DFF,
            nullptr, hh, hl, DM, DM, DM, DFF);

        mmsync<128, 1><<<gP, 256, SMEM128>>>(hh, hl, w2Th + lF, w2Tl + lF, b2 + l * DM,
            tmp, nullptr, nullptr, DFF, DFF, DFF, DM);

        add_ln_split_k<<<SEQ, 256>>>(x, tmp, ln2g + l * DM, ln2b + l * DM, xh, xl);
    }
}